// round 5
// baseline (speedup 1.0000x reference)
#include <cuda_runtime.h>
#include <cstdint>

#define NU 100000
#define NI 50000
#define NN 150000

typedef unsigned long long ull;

// ---------------------------------------------------------------------------
// f32x2 packed-FMA helpers (sm_100+): FFMA2 in SASS, 2x fp32 FMA throughput
// ---------------------------------------------------------------------------
__device__ __forceinline__ ull pack2(float x, float y) {
    ull r; asm("mov.b64 %0, {%1, %2};" : "=l"(r) : "f"(x), "f"(y)); return r;
}
__device__ __forceinline__ float2 unpack2(ull v) {
    float2 r; asm("mov.b64 {%0, %1}, %2;" : "=f"(r.x), "=f"(r.y) : "l"(v)); return r;
}
__device__ __forceinline__ void fma2(ull& d, ull a, ull b) {
    asm("fma.rn.f32x2 %0, %1, %2, %0;" : "+l"(d) : "l"(a), "l"(b));
}

// swizzle for conflict-reduced transposed staging (permutes 4-col groups)
#define SWZ(k, m) ((m) ^ (((k) & 15) << 2))

// ---------------------------------------------------------------------------
// Device-global scratch
// ---------------------------------------------------------------------------
__device__ float g_PT[64 * 32];     // PT[k][i] : transposed score projection (scaled 1/4)
__device__ float g_C[8 * 32];       // C[t0][i] : qoff.koff score constants (scaled)
__device__ float g_WvWo[64 * 64];   // Wv @ Wo
__device__ float g_VoffO[32 * 64];  // VoffO[i][j]
__device__ int   g_ei64;
__device__ int   g_ti64;

__device__ float g_X[(size_t)NN * 64];
__device__ float g_H0[(size_t)NN * 64];
__device__ float g_H1[(size_t)NN * 64];
__device__ float g_AGG[(size_t)NN * 64];

// ---------------------------------------------------------------------------
// Kernel 1: precompute (1 block, 512 threads, shared-staged weights)
// ---------------------------------------------------------------------------
__global__ void __launch_bounds__(512) precompute_kernel(
    const float* __restrict__ te,
    const float* __restrict__ Wq, const float* __restrict__ bq,
    const float* __restrict__ Wk, const float* __restrict__ bk,
    const float* __restrict__ Wv, const float* __restrict__ bv,
    const float* __restrict__ Wo,
    const void* __restrict__ ei_raw, const void* __restrict__ ti_raw)
{
    __shared__ float sWv[4096], sWo[4096], ste[512];
    __shared__ float qoff[512], koff[512], voff[512];
    int t = threadIdx.x;

    for (int i = t; i < 4096; i += 512) { sWv[i] = Wv[i]; sWo[i] = Wo[i]; }
    if (t < 512) ste[t] = te[t];
    __syncthreads();

    {
        int tt = t >> 6, d = t & 63;
        float q = bq[d], k = bk[d], v = bv[d];
        for (int j = 0; j < 64; j++) {
            float x = ste[tt * 64 + j];
            q += x * Wq[j * 64 + d];
            k += x * Wk[j * 64 + d];
            v += x * sWv[j * 64 + d];
        }
        qoff[t] = q; koff[t] = k; voff[t] = v;
    }
    __syncthreads();

    // PT[j][i], i = h*8+t  (transposed score projection, pre-scaled by 1/sqrt(16))
    for (int idx = t; idx < 2048; idx += 512) {
        int j = idx >> 5, i = idx & 31;
        int h = i >> 3, tt = i & 7;
        float s = 0.f;
        #pragma unroll
        for (int m = 0; m < 16; m++)
            s += Wq[j * 64 + h * 16 + m] * koff[tt * 64 + h * 16 + m];
        g_PT[idx] = 0.25f * s;
    }
    // VoffO[i][j]
    for (int idx = t; idx < 2048; idx += 512) {
        int i = idx >> 6, j = idx & 63;
        int h = i >> 3, tt = i & 7;
        float s = 0.f;
        #pragma unroll
        for (int m = 0; m < 16; m++)
            s += voff[tt * 64 + h * 16 + m] * sWo[(h * 16 + m) * 64 + j];
        g_VoffO[idx] = s;
    }
    // C[t0][i]
    for (int idx = t; idx < 256; idx += 512) {
        int t0 = idx >> 5, i = idx & 31;
        int h = i >> 3, tt = i & 7;
        float s = 0.f;
        #pragma unroll
        for (int m = 0; m < 16; m++)
            s += qoff[t0 * 64 + h * 16 + m] * koff[tt * 64 + h * 16 + m];
        g_C[idx] = 0.25f * s;
    }
    // WvWo[k][j]
    for (int idx = t; idx < 4096; idx += 512) {
        int k = idx >> 6, j = idx & 63;
        float s = 0.f;
        for (int d = 0; d < 64; d++) s += sWv[k * 64 + d] * sWo[d * 64 + j];
        g_WvWo[idx] = s;
    }

    if (t == 0) {
        // int64 vs int32 detection: int64 values < 2^31 have zero odd words
        const int* e32 = (const int*)ei_raw;
        const int* t32 = (const int*)ti_raw;
        int is64 = 1;
        for (int i = 0; i < 64; i++) if (e32[2 * i + 1] != 0) { is64 = 0; break; }
        g_ei64 = is64;
        is64 = 1;
        for (int i = 0; i < 64; i++) if (t32[2 * i + 1] != 0) { is64 = 0; break; }
        g_ti64 = is64;
    }
}

// ---------------------------------------------------------------------------
// Kernel 2: node kernel — register-tiled fused attention GEMMs.
// 64-node tiles. 16x16 thread grid: thread = 4 nodes x 4 output cols.
// GEMM1: x@WvWo (K=64,N=64); GEMM2: scores x@P^T (K=64,N=32);
// softmax(8) per (node,head); phase3: attn@VoffO (K=32,N=64) added to acc.
// Writes g_X, g_H0 and zeros g_AGG for the scatter.
// ---------------------------------------------------------------------------
__global__ void __launch_bounds__(256) node_kernel(
    const float* __restrict__ user_emb,
    const float* __restrict__ item_emb,
    const void* __restrict__ ti_raw,
    const float* __restrict__ te,
    const float* __restrict__ bo,
    const float* __restrict__ causal,
    int numTiles)
{
    __shared__ float sXT[64][68];   // transposed x tile (swizzled)
    __shared__ float sW[64][64];    // WvWo
    __shared__ float sS[32][68];    // scores -> attn (transposed [i][m])
    __shared__ float sTE[512];
    __shared__ float sC[256];
    __shared__ float sBO[64];
    __shared__ int   sT0[64];

    int t = threadIdx.x;
    for (int i = t; i < 4096; i += 256) sW[i >> 6][i & 63] = g_WvWo[i];
    for (int i = t; i < 512; i += 256) sTE[i] = te[i];
    sC[t] = g_C[t];
    if (t < 64) sBO[t] = bo[t];
    int ti64 = g_ti64;
    __syncthreads();

    int tx = t & 15, ty = t >> 4;     // map1: nodes ty*4.., cols tx*4..
    int tx2 = t & 7, ty2 = t >> 3;    // map2: nodes ty2*2.., score cols tx2*4..

    for (int tile = blockIdx.x; tile < numTiles; tile += gridDim.x) {
        int base = tile << 6;

        // stage xT (coalesced loads, swizzled transposed stores)
        for (int idx = t; idx < 1024; idx += 256) {
            int kq = idx & 15, m = idx >> 4;
            int n = base + m;
            float4 v = make_float4(0.f, 0.f, 0.f, 0.f);
            if (n < NN) {
                const float* src = (n < NU) ? user_emb + (size_t)n * 64
                                            : item_emb + (size_t)(n - NU) * 64;
                v = __ldg((const float4*)src + kq);
            }
            int k0 = kq * 4;
            sXT[k0 + 0][SWZ(k0 + 0, m)] = v.x;
            sXT[k0 + 1][SWZ(k0 + 1, m)] = v.y;
            sXT[k0 + 2][SWZ(k0 + 2, m)] = v.z;
            sXT[k0 + 3][SWZ(k0 + 3, m)] = v.w;
        }
        if (t < 64) {
            int n = base + t; int tt = 0;
            if (n < NN)
                tt = ti64 ? (int)__ldg((const long long*)ti_raw + n)
                          : __ldg((const int*)ti_raw + n);
            sT0[t] = tt;
        }
        __syncthreads();

        // GEMM1: acc[m][colpair] = x @ WvWo
        ull acc[4][2];
        #pragma unroll
        for (int a = 0; a < 4; a++) { acc[a][0] = 0; acc[a][1] = 0; }
        #pragma unroll 4
        for (int k = 0; k < 64; k++) {
            float4 h = *(const float4*)&sXT[k][SWZ(k, ty * 4)];
            float4 w = *(const float4*)&sW[k][tx * 4];
            ull w01 = pack2(w.x, w.y), w23 = pack2(w.z, w.w);
            ull h0 = pack2(h.x, h.x), h1 = pack2(h.y, h.y);
            ull h2 = pack2(h.z, h.z), h3 = pack2(h.w, h.w);
            fma2(acc[0][0], h0, w01); fma2(acc[0][1], h0, w23);
            fma2(acc[1][0], h1, w01); fma2(acc[1][1], h1, w23);
            fma2(acc[2][0], h2, w01); fma2(acc[2][1], h2, w23);
            fma2(acc[3][0], h3, w01); fma2(acc[3][1], h3, w23);
        }

        // GEMM2: scores (2 nodes x 4 score cols per thread)
        ull accs[2][2];
        accs[0][0] = accs[0][1] = accs[1][0] = accs[1][1] = 0;
        #pragma unroll 4
        for (int k = 0; k < 64; k++) {
            float2 h = *(const float2*)&sXT[k][SWZ(k, ty2 * 2)];
            float4 p = __ldg((const float4*)(g_PT + k * 32 + tx2 * 4));
            ull p01 = pack2(p.x, p.y), p23 = pack2(p.z, p.w);
            ull ha = pack2(h.x, h.x), hb = pack2(h.y, h.y);
            fma2(accs[0][0], ha, p01); fma2(accs[0][1], ha, p23);
            fma2(accs[1][0], hb, p01); fma2(accs[1][1], hb, p23);
        }
        {
            int m0 = ty2 * 2;
            int c0a = sT0[m0] * 32, c0b = sT0[m0 + 1] * 32;
            int i0 = tx2 * 4;
            float2 v;
            v = unpack2(accs[0][0]);
            sS[i0 + 0][m0] = v.x + sC[c0a + i0 + 0];
            sS[i0 + 1][m0] = v.y + sC[c0a + i0 + 1];
            v = unpack2(accs[0][1]);
            sS[i0 + 2][m0] = v.x + sC[c0a + i0 + 2];
            sS[i0 + 3][m0] = v.y + sC[c0a + i0 + 3];
            v = unpack2(accs[1][0]);
            sS[i0 + 0][m0 + 1] = v.x + sC[c0b + i0 + 0];
            sS[i0 + 1][m0 + 1] = v.y + sC[c0b + i0 + 1];
            v = unpack2(accs[1][1]);
            sS[i0 + 2][m0 + 1] = v.x + sC[c0b + i0 + 2];
            sS[i0 + 3][m0 + 1] = v.y + sC[c0b + i0 + 3];
        }
        __syncthreads();

        // softmax over 8 timesteps per (node, head): 64 nodes x 4 heads = 256
        {
            int m = t & 63, h = t >> 6;
            float s[8], mx = -1e30f;
            #pragma unroll
            for (int k = 0; k < 8; k++) { s[k] = sS[h * 8 + k][m]; mx = fmaxf(mx, s[k]); }
            float sum = 0.f;
            #pragma unroll
            for (int k = 0; k < 8; k++) { s[k] = __expf(s[k] - mx); sum += s[k]; }
            float inv = 1.0f / sum;
            #pragma unroll
            for (int k = 0; k < 8; k++) sS[h * 8 + k][m] = s[k] * inv;
        }
        __syncthreads();

        // phase3: acc += attn @ VoffO
        #pragma unroll 4
        for (int k = 0; k < 32; k++) {
            float4 a = *(const float4*)&sS[k][ty * 4];
            float4 w = __ldg((const float4*)(g_VoffO + k * 64 + tx * 4));
            ull w01 = pack2(w.x, w.y), w23 = pack2(w.z, w.w);
            ull a0 = pack2(a.x, a.x), a1 = pack2(a.y, a.y);
            ull a2 = pack2(a.z, a.z), a3 = pack2(a.w, a.w);
            fma2(acc[0][0], a0, w01); fma2(acc[0][1], a0, w23);
            fma2(acc[1][0], a1, w01); fma2(acc[1][1], a1, w23);
            fma2(acc[2][0], a2, w01); fma2(acc[2][1], a2, w23);
            fma2(acc[3][0], a3, w01); fma2(acc[3][1], a3, w23);
        }

        // epilogue: X = x + (acc + bo + te[t0]);  H0 = X + 0.5*causal;  AGG = 0
        int c = tx * 4;
        #pragma unroll
        for (int mm = 0; mm < 4; mm++) {
            int m = ty * 4 + mm;
            int n = base + m;
            if (n >= NN) continue;
            int t0 = sT0[m];
            float2 r01 = unpack2(acc[mm][0]);
            float2 r23 = unpack2(acc[mm][1]);
            float4 X4;
            X4.x = r01.x + sBO[c + 0] + sTE[t0 * 64 + c + 0] + sXT[c + 0][SWZ(c + 0, m)];
            X4.y = r01.y + sBO[c + 1] + sTE[t0 * 64 + c + 1] + sXT[c + 1][SWZ(c + 1, m)];
            X4.z = r23.x + sBO[c + 2] + sTE[t0 * 64 + c + 2] + sXT[c + 2][SWZ(c + 2, m)];
            X4.w = r23.y + sBO[c + 3] + sTE[t0 * 64 + c + 3] + sXT[c + 3][SWZ(c + 3, m)];
            *((float4*)(g_X + (size_t)n * 64) + tx) = X4;
            float4 cz = __ldg((const float4*)(causal + (size_t)n * 64) + tx);
            float4 H4 = make_float4(X4.x + 0.5f * cz.x, X4.y + 0.5f * cz.y,
                                    X4.z + 0.5f * cz.z, X4.w + 0.5f * cz.w);
            *((float4*)(g_H0 + (size_t)n * 64) + tx) = H4;
            *((float4*)(g_AGG + (size_t)n * 64) + tx) = make_float4(0.f, 0.f, 0.f, 0.f);
        }
        __syncthreads();
    }
}

// ---------------------------------------------------------------------------
// Kernel 3: edge scatter (segment_sum). 16 lanes per edge, red.v4.f32.
// (unchanged from R3 — measured at its red-throughput floor)
// ---------------------------------------------------------------------------
__global__ void __launch_bounds__(256) scatter_kernel(
    const void* __restrict__ ei_raw, int E, int mode)
{
    const float* __restrict__ H = mode ? g_H1 : g_H0;
    int gw = (int)((blockIdx.x * (unsigned)blockDim.x + threadIdx.x) >> 5);
    int lane = threadIdx.x & 31;
    int half = lane >> 4, sub = lane & 15;
    long long e = (long long)gw * 2 + half;
    bool valid = (e < (long long)E);
    long long ec = valid ? e : 0;

    long long src, dst;
    if (g_ei64) {
        const long long* p = (const long long*)ei_raw;
        src = p[ec];
        dst = p[(size_t)E + ec];
    } else {
        const int* p = (const int*)ei_raw;
        src = p[ec];
        dst = p[(size_t)E + ec];
    }
    if (valid) {
        float4 v = *((const float4*)(H + (size_t)src * 64) + sub);
        float* dp = g_AGG + (size_t)dst * 64 + sub * 4;
        asm volatile("red.global.add.v4.f32 [%0], {%1,%2,%3,%4};"
                     :: "l"(dp), "f"(v.x), "f"(v.y), "f"(v.z), "f"(v.w)
                     : "memory");
    }
}

// ---------------------------------------------------------------------------
// Kernel 4: dense GNN layer — register-tiled GEMM, K in 2 halves (h then agg),
// weights restaged per half (48KB static smem budget).
// mode 0: relu(h0@Ws + agg@Wn + b) -> g_H1, and re-zero AGG for scatter #2.
// mode 1: out = g_X + relu(h1@Ws + agg@Wn + b), duplicated if dup.
// ---------------------------------------------------------------------------
__global__ void __launch_bounds__(256) dense_kernel(
    const float* __restrict__ Ws, const float* __restrict__ Wn,
    const float* __restrict__ bb,
    float* __restrict__ out, int dup, int numTiles, int mode)
{
    __shared__ float sInT[64][68];
    __shared__ float sW[64][64];
    __shared__ float sB[64];

    int t = threadIdx.x;
    if (t < 64) sB[t] = bb[t];
    int tx = t & 15, ty = t >> 4;
    const float* __restrict__ Hin = mode ? g_H1 : g_H0;

    for (int tile = blockIdx.x; tile < numTiles; tile += gridDim.x) {
        int base = tile << 6;
        ull acc[4][2];
        #pragma unroll
        for (int a = 0; a < 4; a++) { acc[a][0] = 0; acc[a][1] = 0; }

        #pragma unroll
        for (int half = 0; half < 2; half++) {
            const float* W = half ? Wn : Ws;
            __syncthreads();
            for (int i = t; i < 4096; i += 256) sW[i >> 6][i & 63] = __ldg(W + i);
            for (int idx = t; idx < 1024; idx += 256) {
                int kq = idx & 15, m = idx >> 4;
                int n = base + m;
                float4 v = make_float4(0.f, 0.f, 0.f, 0.f);
                if (n < NN) {
                    if (half == 0) {
                        v = __ldg((const float4*)(Hin + (size_t)n * 64) + kq);
                    } else {
                        float4* ap = (float4*)(g_AGG + (size_t)n * 64) + kq;
                        v = *ap;
                        if (mode == 0) *ap = make_float4(0.f, 0.f, 0.f, 0.f);
                    }
                }
                int k0 = kq * 4;
                sInT[k0 + 0][SWZ(k0 + 0, m)] = v.x;
                sInT[k0 + 1][SWZ(k0 + 1, m)] = v.y;
                sInT[k0 + 2][SWZ(k0 + 2, m)] = v.z;
                sInT[k0 + 3][SWZ(k0 + 3, m)] = v.w;
            }
            __syncthreads();
            #pragma unroll 4
            for (int k = 0; k < 64; k++) {
                float4 h = *(const float4*)&sInT[k][SWZ(k, ty * 4)];
                float4 w = *(const float4*)&sW[k][tx * 4];
                ull w01 = pack2(w.x, w.y), w23 = pack2(w.z, w.w);
                ull h0 = pack2(h.x, h.x), h1 = pack2(h.y, h.y);
                ull h2 = pack2(h.z, h.z), h3 = pack2(h.w, h.w);
                fma2(acc[0][0], h0, w01); fma2(acc[0][1], h0, w23);
                fma2(acc[1][0], h1, w01); fma2(acc[1][1], h1, w23);
                fma2(acc[2][0], h2, w01); fma2(acc[2][1], h2, w23);
                fma2(acc[3][0], h3, w01); fma2(acc[3][1], h3, w23);
            }
        }

        int c = tx * 4;
        #pragma unroll
        for (int mm = 0; mm < 4; mm++) {
            int m = ty * 4 + mm, n = base + m;
            if (n >= NN) continue;
            float2 r01 = unpack2(acc[mm][0]);
            float2 r23 = unpack2(acc[mm][1]);
            float4 r;
            r.x = fmaxf(r01.x + sB[c + 0], 0.f);
            r.y = fmaxf(r01.y + sB[c + 1], 0.f);
            r.z = fmaxf(r23.x + sB[c + 2], 0.f);
            r.w = fmaxf(r23.y + sB[c + 3], 0.f);
            if (mode == 0) {
                *((float4*)(g_H1 + (size_t)n * 64) + tx) = r;
            } else {
                float4 xv = __ldg((const float4*)(g_X + (size_t)n * 64) + tx);
                r.x += xv.x; r.y += xv.y; r.z += xv.z; r.w += xv.w;
                *((float4*)(out + (size_t)n * 64) + tx) = r;
                if (dup)
                    *((float4*)(out + (size_t)(NN + n) * 64) + tx) = r;
            }
        }
    }
}

// ---------------------------------------------------------------------------
// kernel_launch
// ---------------------------------------------------------------------------
extern "C" void kernel_launch(void* const* d_in, const int* in_sizes, int n_in,
                              void* d_out, int out_size)
{
    const void*  ei     = d_in[0];
    const void*  ti     = d_in[2];
    const float* user   = (const float*)d_in[3];
    const float* item   = (const float*)d_in[4];
    const float* te     = (const float*)d_in[5];
    const float* causal = (const float*)d_in[6];
    const float* Wq = (const float*)d_in[7],  *bq = (const float*)d_in[8];
    const float* Wk = (const float*)d_in[9],  *bk = (const float*)d_in[10];
    const float* Wv = (const float*)d_in[11], *bv = (const float*)d_in[12];
    const float* Wo = (const float*)d_in[13], *bo = (const float*)d_in[14];
    const float* Ws0 = (const float*)d_in[15], *Wn0 = (const float*)d_in[16];
    const float* b0  = (const float*)d_in[17];
    const float* Ws1 = (const float*)d_in[18], *Wn1 = (const float*)d_in[19];
    const float* b1  = (const float*)d_in[20];

    int E = in_sizes[1];
    float* out = (float*)d_out;
    int dup = (out_size >= 2 * NN * 64) ? 1 : 0;

    int tiles = (NN + 63) / 64;           // 2344
    int scatBlocks = (E + 15) / 16;

    precompute_kernel<<<1, 512>>>(te, Wq, bq, Wk, bk, Wv, bv, Wo, ei, ti);
    node_kernel<<<592, 256>>>(user, item, ti, te, bo, causal, tiles);
    scatter_kernel<<<scatBlocks, 256>>>(ei, E, 0);
    dense_kernel<<<1172, 256>>>(Ws0, Wn0, b0, nullptr, 0, tiles, 0);
    scatter_kernel<<<scatBlocks, 256>>>(ei, E, 1);
    dense_kernel<<<1172, 256>>>(Ws1, Wn1, b1, out, dup, tiles, 1);
}

// round 6
// speedup vs baseline: 1.0029x; 1.0029x over previous
#include <cuda_runtime.h>
#include <cstdint>

#define NU 100000
#define NI 50000
#define NN 150000

typedef unsigned long long ull;

// ---------------------------------------------------------------------------
// f32x2 packed-FMA helpers (Blackwell): FFMA2 in SASS
// ---------------------------------------------------------------------------
__device__ __forceinline__ ull pack2(float x, float y) {
    ull r; asm("mov.b64 %0, {%1, %2};" : "=l"(r) : "f"(x), "f"(y)); return r;
}
__device__ __forceinline__ float2 unpack2(ull v) {
    float2 r; asm("mov.b64 {%0, %1}, %2;" : "=f"(r.x), "=f"(r.y) : "l"(v)); return r;
}
__device__ __forceinline__ void fma2(ull& d, ull a, ull b) {
    asm("fma.rn.f32x2 %0, %1, %2, %0;" : "+l"(d) : "l"(a), "l"(b));
}

// XOR swizzle for conflict-free transposed staging (permutes 4-col groups)
#define SWZ(k, m) ((m) ^ (((k) & 15) << 2))

// ---------------------------------------------------------------------------
// Device-global scratch
// ---------------------------------------------------------------------------
__device__ float g_PT[64 * 32];     // PT[k][i] : transposed score projection (scaled 1/4)
__device__ float g_C[8 * 32];       // C[t0][i] : qoff.koff score constants (scaled)
__device__ float g_WvWo[64 * 64];   // Wv @ Wo
__device__ float g_VoffO[32 * 64];  // VoffO[i][j]
__device__ int   g_ei64;
__device__ int   g_ti64;

__device__ float g_X[(size_t)NN * 64];
__device__ float g_H0[(size_t)NN * 64];
__device__ float g_H1[(size_t)NN * 64];
__device__ float g_AGG[(size_t)NN * 64];

// ---------------------------------------------------------------------------
// Kernel 1: precompute, parallelized over 4 blocks.
// Every block redundantly computes qoff/koff/voff (cheap), then:
//   block 0: PT + C + dtype detection
//   block 1: VoffO
//   block 2: WvWo rows 0-31
//   block 3: WvWo rows 32-63
// ---------------------------------------------------------------------------
__global__ void __launch_bounds__(256) precompute_kernel(
    const float* __restrict__ te,
    const float* __restrict__ Wq, const float* __restrict__ bq,
    const float* __restrict__ Wk, const float* __restrict__ bk,
    const float* __restrict__ Wv, const float* __restrict__ bv,
    const float* __restrict__ Wo,
    const void* __restrict__ ei_raw, const void* __restrict__ ti_raw)
{
    __shared__ float qoff[512], koff[512], voff[512];
    __shared__ float sWo[4096];
    int t = threadIdx.x;
    int blk = blockIdx.x;

    // qoff/koff/voff (each block computes what it needs; all compute all — cheap)
    for (int idx = t; idx < 512; idx += 256) {
        int tt = idx >> 6, d = idx & 63;
        float q = bq[d], k = bk[d], v = bv[d];
        for (int j = 0; j < 64; j++) {
            float x = __ldg(te + tt * 64 + j);
            q += x * __ldg(Wq + j * 64 + d);
            k += x * __ldg(Wk + j * 64 + d);
            v += x * __ldg(Wv + j * 64 + d);
        }
        qoff[idx] = q; koff[idx] = k; voff[idx] = v;
    }
    if (blk == 1 || blk >= 2) {
        for (int i = t; i < 4096; i += 256) sWo[i] = __ldg(Wo + i);
    }
    __syncthreads();

    if (blk == 0) {
        // PT[j][i], i = h*8+t (pre-scaled by 1/sqrt(16))
        for (int idx = t; idx < 2048; idx += 256) {
            int j = idx >> 5, i = idx & 31;
            int h = i >> 3, tt = i & 7;
            float s = 0.f;
            #pragma unroll
            for (int m = 0; m < 16; m++)
                s += __ldg(Wq + j * 64 + h * 16 + m) * koff[tt * 64 + h * 16 + m];
            g_PT[idx] = 0.25f * s;
        }
        // C[t0][i]
        for (int idx = t; idx < 256; idx += 256) {
            int t0 = idx >> 5, i = idx & 31;
            int h = i >> 3, tt = i & 7;
            float s = 0.f;
            #pragma unroll
            for (int m = 0; m < 16; m++)
                s += qoff[t0 * 64 + h * 16 + m] * koff[tt * 64 + h * 16 + m];
            g_C[idx] = 0.25f * s;
        }
        if (t == 0) {
            // int64 detection: int64 values < 2^31 have zero odd 32-bit words
            const int* e32 = (const int*)ei_raw;
            const int* t32 = (const int*)ti_raw;
            int is64 = 1;
            for (int i = 0; i < 64; i++) if (e32[2 * i + 1] != 0) { is64 = 0; break; }
            g_ei64 = is64;
            is64 = 1;
            for (int i = 0; i < 64; i++) if (t32[2 * i + 1] != 0) { is64 = 0; break; }
            g_ti64 = is64;
        }
    } else if (blk == 1) {
        // VoffO[i][j]
        for (int idx = t; idx < 2048; idx += 256) {
            int i = idx >> 6, j = idx & 63;
            int h = i >> 3, tt = i & 7;
            float s = 0.f;
            #pragma unroll
            for (int m = 0; m < 16; m++)
                s += voff[tt * 64 + h * 16 + m] * sWo[(h * 16 + m) * 64 + j];
            g_VoffO[idx] = s;
        }
    } else {
        // WvWo[k][j], 32 rows per block
        int kbase = (blk - 2) * 32;
        int k = kbase + (t >> 3);
        int j0 = (t & 7) * 8;
        float xv[64];
        #pragma unroll 16
        for (int d = 0; d < 64; d++) xv[d] = __ldg(Wv + k * 64 + d);
        float acc[8];
        #pragma unroll
        for (int j = 0; j < 8; j++) acc[j] = 0.f;
        for (int d = 0; d < 64; d++) {
            float x = xv[d];
            #pragma unroll
            for (int j = 0; j < 8; j++) acc[j] += x * sWo[d * 64 + j0 + j];
        }
        #pragma unroll
        for (int j = 0; j < 8; j++) g_WvWo[k * 64 + j0 + j] = acc[j];
    }
}

// ---------------------------------------------------------------------------
// Kernel 2: node kernel — one 64-node tile per block.
// GEMM1: x@WvWo; GEMM2: scores = x@P^T + C[t0]; softmax(8) per (node,head);
// phase3: attn@VoffO added. Writes g_X, g_H0, zeros g_AGG.
// ---------------------------------------------------------------------------
__global__ void __launch_bounds__(256) node_kernel(
    const float* __restrict__ user_emb,
    const float* __restrict__ item_emb,
    const void* __restrict__ ti_raw,
    const float* __restrict__ te,
    const float* __restrict__ bo,
    const float* __restrict__ causal)
{
    __shared__ float sXT[64][68];   // transposed x tile (swizzled)
    __shared__ float sW[64][64];    // WvWo
    __shared__ float sS[32][68];    // scores -> attn ([i][m])
    __shared__ float sTE[512];
    __shared__ float sC[256];
    __shared__ float sBO[64];
    __shared__ int   sT0[64];

    int t = threadIdx.x;
    int ti64 = g_ti64;
    int base = blockIdx.x << 6;

    for (int i = t; i < 4096; i += 256) sW[i >> 6][i & 63] = g_WvWo[i];
    for (int i = t; i < 512; i += 256) sTE[i] = __ldg(te + i);
    sC[t] = g_C[t];
    if (t < 64) sBO[t] = __ldg(bo + t);

    // stage xT (coalesced loads, swizzled transposed stores)
    for (int idx = t; idx < 1024; idx += 256) {
        int kq = idx & 15, m = idx >> 4;
        int n = base + m;
        float4 v = make_float4(0.f, 0.f, 0.f, 0.f);
        if (n < NN) {
            const float* src = (n < NU) ? user_emb + (size_t)n * 64
                                        : item_emb + (size_t)(n - NU) * 64;
            v = __ldg((const float4*)src + kq);
        }
        int k0 = kq * 4;
        sXT[k0 + 0][SWZ(k0 + 0, m)] = v.x;
        sXT[k0 + 1][SWZ(k0 + 1, m)] = v.y;
        sXT[k0 + 2][SWZ(k0 + 2, m)] = v.z;
        sXT[k0 + 3][SWZ(k0 + 3, m)] = v.w;
    }
    if (t < 64) {
        int n = base + t; int tt = 0;
        if (n < NN)
            tt = ti64 ? (int)__ldg((const long long*)ti_raw + n)
                      : __ldg((const int*)ti_raw + n);
        sT0[t] = tt;
    }
    __syncthreads();

    int tx = t & 15, ty = t >> 4;     // map1: nodes ty*4.., cols tx*4..
    int tx2 = t & 7, ty2 = t >> 3;    // map2: nodes ty2*2.., score cols tx2*4..

    // GEMM1: acc = x @ WvWo
    ull acc[4][2];
    #pragma unroll
    for (int a = 0; a < 4; a++) { acc[a][0] = 0; acc[a][1] = 0; }
    #pragma unroll 8
    for (int k = 0; k < 64; k++) {
        float4 h = *(const float4*)&sXT[k][SWZ(k, ty * 4)];
        float4 w = *(const float4*)&sW[k][tx * 4];
        ull w01 = pack2(w.x, w.y), w23 = pack2(w.z, w.w);
        ull h0 = pack2(h.x, h.x), h1 = pack2(h.y, h.y);
        ull h2 = pack2(h.z, h.z), h3 = pack2(h.w, h.w);
        fma2(acc[0][0], h0, w01); fma2(acc[0][1], h0, w23);
        fma2(acc[1][0], h1, w01); fma2(acc[1][1], h1, w23);
        fma2(acc[2][0], h2, w01); fma2(acc[2][1], h2, w23);
        fma2(acc[3][0], h3, w01); fma2(acc[3][1], h3, w23);
    }

    // GEMM2: scores (2 nodes x 4 score cols per thread)
    ull accs[2][2];
    accs[0][0] = accs[0][1] = accs[1][0] = accs[1][1] = 0;
    #pragma unroll 8
    for (int k = 0; k < 64; k++) {
        float2 h = *(const float2*)&sXT[k][SWZ(k, ty2 * 2)];
        float4 p = __ldg((const float4*)(g_PT + k * 32 + tx2 * 4));
        ull p01 = pack2(p.x, p.y), p23 = pack2(p.z, p.w);
        ull ha = pack2(h.x, h.x), hb = pack2(h.y, h.y);
        fma2(accs[0][0], ha, p01); fma2(accs[0][1], ha, p23);
        fma2(accs[1][0], hb, p01); fma2(accs[1][1], hb, p23);
    }
    {
        int m0 = ty2 * 2;
        int c0a = sT0[m0] * 32, c0b = sT0[m0 + 1] * 32;
        int i0 = tx2 * 4;
        float2 v;
        v = unpack2(accs[0][0]);
        sS[i0 + 0][m0] = v.x + sC[c0a + i0 + 0];
        sS[i0 + 1][m0] = v.y + sC[c0a + i0 + 1];
        v = unpack2(accs[0][1]);
        sS[i0 + 2][m0] = v.x + sC[c0a + i0 + 2];
        sS[i0 + 3][m0] = v.y + sC[c0a + i0 + 3];
        v = unpack2(accs[1][0]);
        sS[i0 + 0][m0 + 1] = v.x + sC[c0b + i0 + 0];
        sS[i0 + 1][m0 + 1] = v.y + sC[c0b + i0 + 1];
        v = unpack2(accs[1][1]);
        sS[i0 + 2][m0 + 1] = v.x + sC[c0b + i0 + 2];
        sS[i0 + 3][m0 + 1] = v.y + sC[c0b + i0 + 3];
    }
    __syncthreads();

    // softmax over 8 timesteps per (node, head): 64 nodes x 4 heads = 256 threads
    {
        int m = t & 63, h = t >> 6;
        float s[8], mx = -1e30f;
        #pragma unroll
        for (int k = 0; k < 8; k++) { s[k] = sS[h * 8 + k][m]; mx = fmaxf(mx, s[k]); }
        float sum = 0.f;
        #pragma unroll
        for (int k = 0; k < 8; k++) { s[k] = __expf(s[k] - mx); sum += s[k]; }
        float inv = 1.0f / sum;
        #pragma unroll
        for (int k = 0; k < 8; k++) sS[h * 8 + k][m] = s[k] * inv;
    }
    __syncthreads();

    // phase3: acc += attn @ VoffO
    #pragma unroll 8
    for (int k = 0; k < 32; k++) {
        float4 a = *(const float4*)&sS[k][ty * 4];
        float4 w = __ldg((const float4*)(g_VoffO + k * 64 + tx * 4));
        ull w01 = pack2(w.x, w.y), w23 = pack2(w.z, w.w);
        ull a0 = pack2(a.x, a.x), a1 = pack2(a.y, a.y);
        ull a2 = pack2(a.z, a.z), a3 = pack2(a.w, a.w);
        fma2(acc[0][0], a0, w01); fma2(acc[0][1], a0, w23);
        fma2(acc[1][0], a1, w01); fma2(acc[1][1], a1, w23);
        fma2(acc[2][0], a2, w01); fma2(acc[2][1], a2, w23);
        fma2(acc[3][0], a3, w01); fma2(acc[3][1], a3, w23);
    }

    // epilogue: X = x + (acc + bo + te[t0]);  H0 = X + 0.5*causal;  AGG = 0
    int c = tx * 4;
    #pragma unroll
    for (int mm = 0; mm < 4; mm++) {
        int m = ty * 4 + mm;
        int n = base + m;
        if (n >= NN) continue;
        int t0 = sT0[m];
        float2 r01 = unpack2(acc[mm][0]);
        float2 r23 = unpack2(acc[mm][1]);
        float4 X4;
        X4.x = r01.x + sBO[c + 0] + sTE[t0 * 64 + c + 0] + sXT[c + 0][SWZ(c + 0, m)];
        X4.y = r01.y + sBO[c + 1] + sTE[t0 * 64 + c + 1] + sXT[c + 1][SWZ(c + 1, m)];
        X4.z = r23.x + sBO[c + 2] + sTE[t0 * 64 + c + 2] + sXT[c + 2][SWZ(c + 2, m)];
        X4.w = r23.y + sBO[c + 3] + sTE[t0 * 64 + c + 3] + sXT[c + 3][SWZ(c + 3, m)];
        *((float4*)(g_X + (size_t)n * 64) + tx) = X4;
        float4 cz = __ldg((const float4*)(causal + (size_t)n * 64) + tx);
        float4 H4 = make_float4(X4.x + 0.5f * cz.x, X4.y + 0.5f * cz.y,
                                X4.z + 0.5f * cz.z, X4.w + 0.5f * cz.w);
        *((float4*)(g_H0 + (size_t)n * 64) + tx) = H4;
        *((float4*)(g_AGG + (size_t)n * 64) + tx) = make_float4(0.f, 0.f, 0.f, 0.f);
    }
}

// ---------------------------------------------------------------------------
// Kernel 3: edge scatter (segment_sum). 16 lanes per edge, red.v4.f32.
// Measured at the REDG lane-issue floor (~1.29 cyc/lane) — unchanged.
// ---------------------------------------------------------------------------
__global__ void __launch_bounds__(256) scatter_kernel(
    const void* __restrict__ ei_raw, int E, int mode)
{
    const float* __restrict__ H = mode ? g_H1 : g_H0;
    int gw = (int)((blockIdx.x * (unsigned)blockDim.x + threadIdx.x) >> 5);
    int lane = threadIdx.x & 31;
    int half = lane >> 4, sub = lane & 15;
    long long e = (long long)gw * 2 + half;
    bool valid = (e < (long long)E);
    long long ec = valid ? e : 0;

    long long src, dst;
    if (g_ei64) {
        const long long* p = (const long long*)ei_raw;
        src = p[ec];
        dst = p[(size_t)E + ec];
    } else {
        const int* p = (const int*)ei_raw;
        src = p[ec];
        dst = p[(size_t)E + ec];
    }
    if (valid) {
        float4 v = *((const float4*)(H + (size_t)src * 64) + sub);
        float* dp = g_AGG + (size_t)dst * 64 + sub * 4;
        asm volatile("red.global.add.v4.f32 [%0], {%1,%2,%3,%4};"
                     :: "l"(dp), "f"(v.x), "f"(v.y), "f"(v.z), "f"(v.w)
                     : "memory");
    }
}

// ---------------------------------------------------------------------------
// Kernel 4: dense GNN layer — one 64-node tile per block.
// Weights for BOTH K-halves resident in smem for the whole block (32KB);
// input restaged per half (16KB, XOR swizzle). 48KB static total.
// mode 0: relu(h0@Ws + agg@Wn + b) -> g_H1, re-zeroing AGG for scatter #2.
// mode 1: out = g_X + relu(h1@Ws + agg@Wn + b), duplicated if dup.
// ---------------------------------------------------------------------------
__global__ void __launch_bounds__(256) dense_kernel(
    const float* __restrict__ Ws, const float* __restrict__ Wn,
    const float* __restrict__ bb,
    float* __restrict__ out, int dup, int mode)
{
    __shared__ float sW[2][64][64];   // 32 KB : [0]=Ws, [1]=Wn
    __shared__ float sIn[64][64];     // 16 KB : XOR-swizzled transposed input

    int t = threadIdx.x;
    int tx = t & 15, ty = t >> 4;
    int base = blockIdx.x << 6;
    const float* __restrict__ Hin = mode ? g_H1 : g_H0;

    // stage both weight matrices once (coalesced float4)
    {
        float4* dst = (float4*)sW;
        const float4* s0 = (const float4*)Ws;
        const float4* s1 = (const float4*)Wn;
        for (int i = t; i < 1024; i += 256) {
            dst[i]        = __ldg(s0 + i);
            dst[1024 + i] = __ldg(s1 + i);
        }
    }

    ull acc[4][2];
    #pragma unroll
    for (int a = 0; a < 4; a++) { acc[a][0] = 0; acc[a][1] = 0; }

    #pragma unroll
    for (int half = 0; half < 2; half++) {
        if (half) __syncthreads();           // protect sIn reuse
        // stage input half (h or agg), transposed + swizzled
        for (int idx = t; idx < 1024; idx += 256) {
            int kq = idx & 15, m = idx >> 4;
            int n = base + m;
            float4 v = make_float4(0.f, 0.f, 0.f, 0.f);
            if (n < NN) {
                if (half == 0) {
                    v = __ldg((const float4*)(Hin + (size_t)n * 64) + kq);
                } else {
                    float4* ap = (float4*)(g_AGG + (size_t)n * 64) + kq;
                    v = *ap;
                    if (mode == 0) *ap = make_float4(0.f, 0.f, 0.f, 0.f);
                }
            }
            int k0 = kq * 4;
            sIn[k0 + 0][SWZ(k0 + 0, m)] = v.x;
            sIn[k0 + 1][SWZ(k0 + 1, m)] = v.y;
            sIn[k0 + 2][SWZ(k0 + 2, m)] = v.z;
            sIn[k0 + 3][SWZ(k0 + 3, m)] = v.w;
        }
        __syncthreads();

        #pragma unroll 8
        for (int k = 0; k < 64; k++) {
            float4 h = *(const float4*)&sIn[k][SWZ(k, ty * 4)];
            float4 w = *(const float4*)&sW[half][k][tx * 4];
            ull w01 = pack2(w.x, w.y), w23 = pack2(w.z, w.w);
            ull h0 = pack2(h.x, h.x), h1 = pack2(h.y, h.y);
            ull h2 = pack2(h.z, h.z), h3 = pack2(h.w, h.w);
            fma2(acc[0][0], h0, w01); fma2(acc[0][1], h0, w23);
            fma2(acc[1][0], h1, w01); fma2(acc[1][1], h1, w23);
            fma2(acc[2][0], h2, w01); fma2(acc[2][1], h2, w23);
            fma2(acc[3][0], h3, w01); fma2(acc[3][1], h3, w23);
        }
    }

    // epilogue
    int c = tx * 4;
    float4 bv = __ldg((const float4*)bb + tx);
    #pragma unroll
    for (int mm = 0; mm < 4; mm++) {
        int m = ty * 4 + mm, n = base + m;
        if (n >= NN) continue;
        float2 r01 = unpack2(acc[mm][0]);
        float2 r23 = unpack2(acc[mm][1]);
        float4 r;
        r.x = fmaxf(r01.x + bv.x, 0.f);
        r.y = fmaxf(r01.y + bv.y, 0.f);
        r.z = fmaxf(r23.x + bv.z, 0.f);
        r.w = fmaxf(r23.y + bv.w, 0.f);
        if (mode == 0) {
            *((float4*)(g_H1 + (size_t)n * 64) + tx) = r;
        } else {
            float4 xv = __ldg((const float4*)(g_X + (size_t)n * 64) + tx);
            r.x += xv.x; r.y += xv.y; r.z += xv.z; r.w += xv.w;
            *((float4*)(out + (size_t)n * 64) + tx) = r;
            if (dup)
                *((float4*)(out + (size_t)(NN + n) * 64) + tx) = r;
        }
    }
}

// ---------------------------------------------------------------------------
// kernel_launch
// ---------------------------------------------------------------------------
extern "C" void kernel_launch(void* const* d_in, const int* in_sizes, int n_in,
                              void* d_out, int out_size)
{
    const void*  ei     = d_in[0];
    const void*  ti     = d_in[2];
    const float* user   = (const float*)d_in[3];
    const float* item   = (const float*)d_in[4];
    const float* te     = (const float*)d_in[5];
    const float* causal = (const float*)d_in[6];
    const float* Wq = (const float*)d_in[7],  *bq = (const float*)d_in[8];
    const float* Wk = (const float*)d_in[9],  *bk = (const float*)d_in[10];
    const float* Wv = (const float*)d_in[11], *bv = (const float*)d_in[12];
    const float* Wo = (const float*)d_in[13], *bo = (const float*)d_in[14];
    const float* Ws0 = (const float*)d_in[15], *Wn0 = (const float*)d_in[16];
    const float* b0  = (const float*)d_in[17];
    const float* Ws1 = (const float*)d_in[18], *Wn1 = (const float*)d_in[19];
    const float* b1  = (const float*)d_in[20];

    int E = in_sizes[1];
    float* out = (float*)d_out;
    int dup = (out_size >= 2 * NN * 64) ? 1 : 0;

    int tiles = (NN + 63) / 64;           // 2344
    int scatBlocks = (E + 15) / 16;

    precompute_kernel<<<4, 256>>>(te, Wq, bq, Wk, bk, Wv, bv, Wo, ei, ti);
    node_kernel<<<tiles, 256>>>(user, item, ti, te, bo, causal);
    scatter_kernel<<<scatBlocks, 256>>>(ei, E, 0);
    dense_kernel<<<tiles, 256>>>(Ws0, Wn0, b0, nullptr, 0, 0);
    scatter_kernel<<<scatBlocks, 256>>>(ei, E, 1);
    dense_kernel<<<tiles, 256>>>(Ws1, Wn1, b1, out, dup, 1);
}